// round 11
// baseline (speedup 1.0000x reference)
#include <cuda_runtime.h>
#include <cuda_bf16.h>
#include <cstdint>

// Problem constants (DioLstm: B=4, NWORD=24, HID=512)
#define BD 4
#define NW 24
#define HD 512
#define H2 1024
#define H5 2560

// ---------------------------------------------------------------------------
// Device globals (no allocs)
// ---------------------------------------------------------------------------
__device__ __align__(16) float g_chartH[BD*NW*NW*HD];
__device__ __align__(16) float g_chartC[BD*NW*NW*HD];
__device__ float g_chartS[BD*NW*NW];
__device__ __align__(16) float g_Ui[BD*NW*NW*H5];
__device__ __align__(16) float g_Us[BD*NW*NW*H5];
__device__ __align__(16) float g_aL1[BD*NW*NW*H2];   // bilinear, k in [0,512)
__device__ __align__(16) float g_aL2[BD*NW*NW*H2];   // bilinear, k in [512,1024)
__device__ float g_bias[H5];
// bf16 2-term-split weights: W1 = [Wi; Ws] (5120 x 512); Wbt = Wbil^T (1024 x 1024)
__device__ __align__(16) __nv_bfloat16 g_W1hi[5120*512];
__device__ __align__(16) __nv_bfloat16 g_W1lo[5120*512];
__device__ __align__(16) __nv_bfloat16 g_Wbhi[1024*1024];
__device__ __align__(16) __nv_bfloat16 g_Wblo[1024*1024];
// bf16 split activations for current diagonal: rows = cell m (<=96, pad 128), k = [h|c]
__device__ __align__(16) __nv_bfloat16 g_Ahi[128*H2];
__device__ __align__(16) __nv_bfloat16 g_Alo[128*H2];

__device__ __forceinline__ int cellIdx(int b, int left, int len) {
    return (b*NW + left)*NW + len;
}
__device__ __forceinline__ float sigf(float x) {
    return __fdividef(1.0f, 1.0f + __expf(-x));
}
__device__ __forceinline__ float tanhx(float x) {
    return __fdividef(2.0f, 1.0f + __expf(-2.0f*x)) - 1.0f;
}

// m16n8k16 row.col bf16 MMA, fp32 accum (sm_80+ family-stable PTX)
#define MMA_BF16(C, A0, A1, A2, A3, B0, B1) \
    asm volatile("mma.sync.aligned.m16n8k16.row.col.f32.bf16.bf16.f32 " \
        "{%0,%1,%2,%3}, {%4,%5,%6,%7}, {%8,%9}, {%0,%1,%2,%3};" \
        : "+f"((C)[0]), "+f"((C)[1]), "+f"((C)[2]), "+f"((C)[3]) \
        : "r"(A0), "r"(A1), "r"(A2), "r"(A3), "r"(B0), "r"(B1))

__device__ __forceinline__ uint32_t lds32(const __nv_bfloat16* p) {
    return *(const uint32_t*)p;
}

// ---------------------------------------------------------------------------
// Launch #0: split weights into bf16 hi/lo. z=0: W1=[Wi;Ws]; z=1: Wbt=Wbil^T.
// ---------------------------------------------------------------------------
__global__ void convW(const float* __restrict__ Wi, const float* __restrict__ Ws,
                      const float* __restrict__ Wbil) {
    int idx = blockIdx.x*256 + threadIdx.x;
    if (blockIdx.z == 0) {
        if (idx < 5120*512) {
            int r = idx >> 9, k = idx & 511;
            float w = (r < 2560) ? Wi[r*512 + k] : Ws[(r - 2560)*512 + k];
            __nv_bfloat16 h = __float2bfloat16(w);
            g_W1hi[idx] = h;
            g_W1lo[idx] = __float2bfloat16(w - __bfloat162float(h));
        }
    } else {
        if (idx < 1024*1024) {
            int o = idx >> 10, k = idx & 1023;
            float w = Wbil[k*1024 + o];
            __nv_bfloat16 h = __float2bfloat16(w);
            g_Wbhi[idx] = h;
            g_Wblo[idx] = __float2bfloat16(w - __bfloat162float(h));
        }
    }
}

// Launch #1: leaves + combined bias.
__global__ void initK(const float* __restrict__ seqt,
                      const float* __restrict__ bi,
                      const float* __restrict__ bs) {
    int idx = blockIdx.x*256 + threadIdx.x;
    if (idx < BD*NW*HD) {
        int i = idx % HD;
        int w = (idx / HD) % NW;
        int b = idx / (HD*NW);
        int c = cellIdx(b, w, 0);
        g_chartH[(size_t)c*HD + i] = seqt[(b*NW + w)*H2 + i];
        g_chartC[(size_t)c*HD + i] = seqt[(b*NW + w)*H2 + HD + i];
        if (i == 0) g_chartS[c] = 0.0f;
    }
    if (idx < H5) {
        float extra = (idx >= HD && idx < 3*HD) ? 1.0f : 0.0f;
        g_bias[idx] = bi[idx] + bs[idx] + extra;
    }
}

// Per-diagonal: split the cells' [h|c] into bf16 hi/lo A rows.
__global__ void convA(int L, int P) {
    int idx = blockIdx.x*256 + threadIdx.x;
    int M = BD*P;
    if (idx >= M*H2) return;
    int m = idx >> 10, i = idx & (H2 - 1);
    int b = m / P, left = m - b*P;
    int ci = cellIdx(b, left, L);
    float x = (i < HD) ? g_chartH[(size_t)ci*HD + i]
                       : g_chartC[(size_t)ci*HD + (i - HD)];
    __nv_bfloat16 h = __float2bfloat16(x);
    g_Ahi[idx] = h;
    g_Alo[idx] = __float2bfloat16(x - __bfloat162float(h));
}

// ---------------------------------------------------------------------------
// HMMA projection GEMM (mma.sync m16n8k16 bf16, 3-plane split, fp32 accum).
// grid (112, mB): x<80 -> W1 n-tile of 64 (K=512); x>=80 -> Wbil n-tile of 64
// split in two K-halves (kh) writing aL1/aL2. Block tile M48 x N64, 4 warps
// (warp = n16 x m48). K staged in 64-chunks, smem rows padded to 72 bf16.
// ---------------------------------------------------------------------------
__global__ void __launch_bounds__(128) mmaProj(int L, int P) {
    __shared__ __nv_bfloat16 sA[2][48][72];
    __shared__ __nv_bfloat16 sB[2][64][72];
    const int tid = threadIdx.x, lane = tid & 31, warp = tid >> 5;
    const int x = blockIdx.x;
    const int m0 = blockIdx.y * 48;
    const int M = BD * P;

    const __nv_bfloat16 *Wh, *Wl;
    float* dstBase; int oSeg; size_t stride; int wK, kofs, nrow0;
    if (x < 80) {
        int n0 = x * 64;
        Wh = g_W1hi; Wl = g_W1lo; wK = 512; kofs = 0; nrow0 = n0;
        if (n0 < H5) { dstBase = g_Ui; oSeg = n0; }
        else         { dstBase = g_Us; oSeg = n0 - H5; }
        stride = H5;
    } else {
        int y = x - 80, wt = y >> 1, kh = y & 1;
        Wh = g_Wbhi; Wl = g_Wblo; wK = 1024; kofs = kh * 512; nrow0 = wt * 64;
        dstBase = kh ? g_aL2 : g_aL1; oSeg = wt * 64; stride = H2;
    }

    float C[3][2][4];
    #pragma unroll
    for (int mt = 0; mt < 3; mt++)
        #pragma unroll
        for (int nt = 0; nt < 2; nt++)
            #pragma unroll
            for (int j = 0; j < 4; j++) C[mt][nt][j] = 0.0f;

    for (int kc = 0; kc < 8; kc++) {
        __syncthreads();
        const int kO = kofs + kc * 64;
        // stage A: 48 rows x 64 k x 2 planes (uint4 = 8 bf16)
        for (int i = tid; i < 48*8; i += 128) {
            int r = i >> 3, j = i & 7;
            const uint4* sh = (const uint4*)(g_Ahi + (size_t)(m0 + r)*H2 + kO + j*8);
            const uint4* sl = (const uint4*)(g_Alo + (size_t)(m0 + r)*H2 + kO + j*8);
            *(uint4*)((char*)&sA[0][r][0] + j*16) = *sh;
            *(uint4*)((char*)&sA[1][r][0] + j*16) = *sl;
        }
        // stage B: 64 weight rows x 64 k x 2 planes
        for (int i = tid; i < 64*8; i += 128) {
            int r = i >> 3, j = i & 7;
            size_t off = (size_t)(nrow0 + r)*wK + kO + j*8;
            *(uint4*)((char*)&sB[0][r][0] + j*16) = *(const uint4*)(Wh + off);
            *(uint4*)((char*)&sB[1][r][0] + j*16) = *(const uint4*)(Wl + off);
        }
        __syncthreads();

        #pragma unroll
        for (int s = 0; s < 4; s++) {
            const int kb = s*16 + ((lane & 3) << 1);
            const int ra = lane >> 2;
            uint32_t ah[3][4], al[3][4];
            #pragma unroll
            for (int mt = 0; mt < 3; mt++) {
                int r0 = mt*16 + ra;
                ah[mt][0] = lds32(&sA[0][r0    ][kb    ]);
                ah[mt][1] = lds32(&sA[0][r0 + 8][kb    ]);
                ah[mt][2] = lds32(&sA[0][r0    ][kb + 8]);
                ah[mt][3] = lds32(&sA[0][r0 + 8][kb + 8]);
                al[mt][0] = lds32(&sA[1][r0    ][kb    ]);
                al[mt][1] = lds32(&sA[1][r0 + 8][kb    ]);
                al[mt][2] = lds32(&sA[1][r0    ][kb + 8]);
                al[mt][3] = lds32(&sA[1][r0 + 8][kb + 8]);
            }
            #pragma unroll
            for (int nt = 0; nt < 2; nt++) {
                int nr = warp*16 + nt*8 + ra;
                uint32_t bh0 = lds32(&sB[0][nr][kb    ]);
                uint32_t bh1 = lds32(&sB[0][nr][kb + 8]);
                uint32_t bl0 = lds32(&sB[1][nr][kb    ]);
                uint32_t bl1 = lds32(&sB[1][nr][kb + 8]);
                #pragma unroll
                for (int mt = 0; mt < 3; mt++) {
                    MMA_BF16(C[mt][nt], ah[mt][0], ah[mt][1], ah[mt][2], ah[mt][3], bh0, bh1);
                    MMA_BF16(C[mt][nt], ah[mt][0], ah[mt][1], ah[mt][2], ah[mt][3], bl0, bl1);
                    MMA_BF16(C[mt][nt], al[mt][0], al[mt][1], al[mt][2], al[mt][3], bh0, bh1);
                }
            }
        }
    }

    // epilogue: C row = lane/4 (+8), col pair = 2*(lane%4)
    #pragma unroll
    for (int mt = 0; mt < 3; mt++) {
        #pragma unroll
        for (int h = 0; h < 2; h++) {
            int m = m0 + mt*16 + (lane >> 2) + h*8;
            if (m < M) {
                int b = m / P, left = m - b*P;
                int ci = cellIdx(b, left, L);
                float* dr = dstBase + (size_t)ci*stride + oSeg;
                #pragma unroll
                for (int nt = 0; nt < 2; nt++) {
                    int o = warp*16 + nt*8 + ((lane & 3) << 1);
                    *(float2*)(dr + o) = make_float2(C[mt][nt][h*2], C[mt][nt][h*2 + 1]);
                }
            }
        }
    }
}

// ---------------------------------------------------------------------------
// Pairs kernel: compat + softmax + gated combine. aL = aL1 + aL2 at use.
// ---------------------------------------------------------------------------
__global__ void pairsK(int L, int SPLIT, float* __restrict__ out) {
    const int P = NW - L;
    const int npair = BD*P;
    const int pairId = blockIdx.x % npair;
    const int s = blockIdx.x / npair;
    const int b = pairId / P, left = pairId - b*P;
    const int chunk = blockDim.x;
    const int e0 = s * chunk;

    __shared__ float s_w[24];
    __shared__ float s_comp[24];
    __shared__ int   s_offL[24], s_offR[24];

    const int tid = threadIdx.x, warp = tid >> 5, lane = tid & 31;
    const int nw = blockDim.x >> 5;

    for (int k = warp; k < L; k += nw) {
        int r = left + k + 1, rl = L - 1 - k;
        int cl = cellIdx(b, left, k), cr = cellIdx(b, r, rl);
        const float* a1 = g_aL1 + (size_t)cl*H2;
        const float* a2 = g_aL2 + (size_t)cl*H2;
        const float* rh = g_chartH + (size_t)cr*HD;
        const float* rc = g_chartC + (size_t)cr*HD;
        float acc = 0.0f;
        for (int i = lane; i < HD; i += 32) {
            acc = fmaf(a1[i] + a2[i], rh[i], acc);
            acc = fmaf(a1[HD + i] + a2[HD + i], rc[i], acc);
        }
        #pragma unroll
        for (int off = 16; off; off >>= 1)
            acc += __shfl_down_sync(0xffffffffu, acc, off);
        if (lane == 0) {
            s_comp[k] = acc + g_chartS[cl] + g_chartS[cr];
            s_offL[k] = cl; s_offR[k] = cr;
        }
    }
    __syncthreads();

    if (warp == 0) {
        float c = (lane < L) ? s_comp[lane] : -3.402823466e38f;
        float m = c;
        #pragma unroll
        for (int off = 16; off; off >>= 1)
            m = fmaxf(m, __shfl_xor_sync(0xffffffffu, m, off));
        float e = (lane < L) ? __expf(c - m) : 0.0f;
        float ssum = e;
        #pragma unroll
        for (int off = 16; off; off >>= 1)
            ssum += __shfl_xor_sync(0xffffffffu, ssum, off);
        float w = __fdividef(e, ssum);
        if (lane < L) s_w[lane] = w;
        float sn = (lane < L) ? w * c : 0.0f;
        #pragma unroll
        for (int off = 16; off; off >>= 1)
            sn += __shfl_xor_sync(0xffffffffu, sn, off);
        if (lane == 0 && s == 0) g_chartS[cellIdx(b, left, L)] = sn;
    }
    __syncthreads();

    {
        int e = e0 + tid;
        float b0 = g_bias[e],        b1 = g_bias[HD + e],  b2 = g_bias[2*HD + e];
        float b3 = g_bias[3*HD + e], b4 = g_bias[4*HD + e];
        float ah = 0.0f, ac = 0.0f;
        for (int k = 0; k < L; k++) {
            int cl = s_offL[k], cr = s_offR[k];
            const float* ui = g_Ui + (size_t)cl*H5;
            const float* us = g_Us + (size_t)cr*H5;
            float p0 = ui[e]        + us[e]        + b0;
            float p1 = ui[HD + e]   + us[HD + e]   + b1;
            float p2 = ui[2*HD + e] + us[2*HD + e] + b2;
            float p3 = ui[3*HD + e] + us[3*HD + e] + b3;
            float p4 = ui[4*HD + e] + us[4*HD + e] + b4;
            float lc = g_chartC[(size_t)cl*HD + e];
            float rc = g_chartC[(size_t)cr*HD + e];
            float ig = sigf(p0), lf = sigf(p1), rf = sigf(p2), og = sigf(p4);
            float gg = tanhx(p3);
            float mem = fmaf(lf, lc, fmaf(rf, rc, ig * gg));
            float hh = og * tanhx(mem);
            float w = s_w[k];
            ah = fmaf(w, hh, ah);
            ac = fmaf(w, mem, ac);
        }
        int cn = cellIdx(b, left, L);
        g_chartH[(size_t)cn*HD + e] = ah;
        g_chartC[(size_t)cn*HD + e] = ac;
        if (out) {
            out[b*H2 + e]      = ah;
            out[b*H2 + HD + e] = ac;
        }
    }
}

// ---------------------------------------------------------------------------
// Host side
// ---------------------------------------------------------------------------
static void launchProj(int L, int P) {
    int M = BD * P;
    convA<<<(M*H2 + 255)/256, 256>>>(L, P);
    int mB = (M + 47) / 48;
    mmaProj<<<dim3(112, mB), 128>>>(L, P);
}

static int pickSplit(int P) {
    int np = BD * P;
    if (np >= 64) return 4;   // chunk 128
    return 8;                 // chunk 64
}

extern "C" void kernel_launch(void* const* d_in, const int* in_sizes, int n_in,
                              void* d_out, int out_size) {
    const float* seqt = (const float*)d_in[0];
    const float* Wi   = (const float*)d_in[1];
    const float* bi   = (const float*)d_in[2];
    const float* Ws   = (const float*)d_in[3];
    const float* bs   = (const float*)d_in[4];
    const float* Wbil = (const float*)d_in[5];
    float* out = (float*)d_out;

    // Setup: #0 convW, #1 initK, #2 convA(0) => ncu capture (#3) = mmaProj(L=0)
    convW<<<dim3((5120*512 + 255)/256, 1, 2), 256>>>(Wi, Ws, Wbil);
    initK<<<192, 256>>>(seqt, bi, bs);
    launchProj(0, NW);

    for (int L = 1; L < NW; L++) {
        int P = NW - L;
        int SPLIT = pickSplit(P);
        pairsK<<<BD*P*SPLIT, HD/SPLIT>>>(L, SPLIT, (L == NW - 1) ? out : nullptr);
        if (L < NW - 1) launchProj(L, P);
    }
}

// round 13
// speedup vs baseline: 1.0394x; 1.0394x over previous
#include <cuda_runtime.h>
#include <cuda_bf16.h>
#include <cstdint>

// Problem constants (DioLstm: B=4, NWORD=24, HID=512)
#define BD 4
#define NW 24
#define HD 512
#define H2 1024
#define H5 2560

// ---------------------------------------------------------------------------
// Device globals (no allocs)
// ---------------------------------------------------------------------------
__device__ __align__(16) float g_chartH[BD*NW*NW*HD];
__device__ __align__(16) float g_chartC[BD*NW*NW*HD];
__device__ float g_chartS[BD*NW*NW];
__device__ __align__(16) float g_Ui[BD*NW*NW*H5];
__device__ __align__(16) float g_Us[BD*NW*NW*H5];
__device__ __align__(16) float g_aL1[BD*NW*NW*H2];   // bilinear, k in [0,512)
__device__ __align__(16) float g_aL2[BD*NW*NW*H2];   // bilinear, k in [512,1024)
__device__ float g_bias[H5];
// bf16 2-term-split weights: W1 = [Wi; Ws] (5120 x 512); Wbt = Wbil^T (1024 x 1024)
__device__ __align__(16) __nv_bfloat16 g_W1hi[5120*512];
__device__ __align__(16) __nv_bfloat16 g_W1lo[5120*512];
__device__ __align__(16) __nv_bfloat16 g_Wbhi[1024*1024];
__device__ __align__(16) __nv_bfloat16 g_Wblo[1024*1024];

__device__ __forceinline__ int cellIdx(int b, int left, int len) {
    return (b*NW + left)*NW + len;
}
__device__ __forceinline__ float sigf(float x) {
    return __fdividef(1.0f, 1.0f + __expf(-x));
}
__device__ __forceinline__ float tanhx(float x) {
    return __fdividef(2.0f, 1.0f + __expf(-2.0f*x)) - 1.0f;
}

// m16n8k16 row.col bf16 MMA, fp32 accum (sm_80+ family-stable PTX)
#define MMA_BF16(C, A0, A1, A2, A3, B0, B1) \
    asm volatile("mma.sync.aligned.m16n8k16.row.col.f32.bf16.bf16.f32 " \
        "{%0,%1,%2,%3}, {%4,%5,%6,%7}, {%8,%9}, {%0,%1,%2,%3};" \
        : "+f"((C)[0]), "+f"((C)[1]), "+f"((C)[2]), "+f"((C)[3]) \
        : "r"(A0), "r"(A1), "r"(A2), "r"(A3), "r"(B0), "r"(B1))

__device__ __forceinline__ uint32_t lds32(const __nv_bfloat16* p) {
    return *(const uint32_t*)p;
}

// ---------------------------------------------------------------------------
// Launch #0: split weights into bf16 hi/lo. z=0: W1=[Wi;Ws]; z=1: Wbt=Wbil^T.
// ---------------------------------------------------------------------------
__global__ void convW(const float* __restrict__ Wi, const float* __restrict__ Ws,
                      const float* __restrict__ Wbil) {
    int idx = blockIdx.x*256 + threadIdx.x;
    if (blockIdx.z == 0) {
        if (idx < 5120*512) {
            int r = idx >> 9, k = idx & 511;
            float w = (r < 2560) ? Wi[r*512 + k] : Ws[(r - 2560)*512 + k];
            __nv_bfloat16 h = __float2bfloat16(w);
            g_W1hi[idx] = h;
            g_W1lo[idx] = __float2bfloat16(w - __bfloat162float(h));
        }
    } else {
        if (idx < 1024*1024) {
            int o = idx >> 10, k = idx & 1023;
            float w = Wbil[k*1024 + o];
            __nv_bfloat16 h = __float2bfloat16(w);
            g_Wbhi[idx] = h;
            g_Wblo[idx] = __float2bfloat16(w - __bfloat162float(h));
        }
    }
}

// Launch #1: leaves.
__global__ void initLeaves(const float* __restrict__ seqt) {
    int idx = blockIdx.x*256 + threadIdx.x;
    if (idx < BD*NW*HD) {
        int i = idx % HD;
        int w = (idx / HD) % NW;
        int b = idx / (HD*NW);
        int c = cellIdx(b, w, 0);
        g_chartH[(size_t)c*HD + i] = seqt[(b*NW + w)*H2 + i];
        g_chartC[(size_t)c*HD + i] = seqt[(b*NW + w)*H2 + HD + i];
        if (i == 0) g_chartS[c] = 0.0f;
    }
}

// Launch #2: combined bias (separate so ncu -s lands #3 on mmaProj(L=0)).
__global__ void initBias(const float* __restrict__ bi, const float* __restrict__ bs) {
    int idx = blockIdx.x*256 + threadIdx.x;
    if (idx < H5) {
        float extra = (idx >= HD && idx < 3*HD) ? 1.0f : 0.0f;
        g_bias[idx] = bi[idx] + bs[idx] + extra;
    }
}

// ---------------------------------------------------------------------------
// HMMA projection GEMM, fused A-conversion, 2 K-group warps.
// grid (224, mB), 256 thr (8 warps = 2 kg x 4 n-warps), block tile M48 x N32.
// x<160: W1 n-tile (K=512); x>=160: Wbt n-tile, kh K-half -> aL1/aL2.
// Each kg handles alternate 64-chunks (4 each); kg1's C added via smem.
// A staged from fp32 chart with in-register bf16 hi/lo split.
// smem (dynamic, 46080 B): sA[2kg][2pl][48][72] bf16 | sB[2kg][2pl][32][72]
// bf16; sC (kg reduction, 6144 B) aliases sA after the k-loop.
// ---------------------------------------------------------------------------
#define SA_OFF 0
#define SB_OFF 27648
#define SM_TOT 46080

__global__ void __launch_bounds__(256) mmaProj(int L, int P) {
    extern __shared__ __align__(16) char smraw[];
    __nv_bfloat16* sA = (__nv_bfloat16*)(smraw + SA_OFF);  // [kg][pl][48][72]
    __nv_bfloat16* sB = (__nv_bfloat16*)(smraw + SB_OFF);  // [kg][pl][32][72]
    float*         sC = (float*)(smraw + SA_OFF);          // aliases sA (post-loop)

    const int tid = threadIdx.x, lane = tid & 31, warp = tid >> 5;
    const int kg = warp >> 2, nw = warp & 3;
    const int x = blockIdx.x;
    const int m0 = blockIdx.y * 48;
    const int M = BD * P;

    const __nv_bfloat16 *Wh, *Wl;
    float* dstBase; int oSeg; size_t stride; int wK, kofs, nrow0; bool bil;
    if (x < 160) {
        int n0 = x * 32;
        Wh = g_W1hi; Wl = g_W1lo; wK = 512; kofs = 0; nrow0 = n0; bil = false;
        if (n0 < H5) { dstBase = g_Ui; oSeg = n0; }
        else         { dstBase = g_Us; oSeg = n0 - H5; }
        stride = H5;
    } else {
        int y = x - 160, wt = y >> 1, kh = y & 1;
        Wh = g_Wbhi; Wl = g_Wblo; wK = 1024; kofs = kh * 512; nrow0 = wt * 32;
        dstBase = kh ? g_aL2 : g_aL1; oSeg = wt * 32; stride = H2; bil = true;
    }

    float C[3][4];
    #pragma unroll
    for (int mt = 0; mt < 3; mt++)
        #pragma unroll
        for (int j = 0; j < 4; j++) C[mt][j] = 0.0f;

    for (int t = 0; t < 4; t++) {
        __syncthreads();   // previous chunk compute done before restage

        // ---- stage A (fp32 -> bf16 hi/lo), both kg chunks: 2*768 iters ----
        for (int i = tid; i < 2*48*16; i += 256) {
            int akg = (i >= 768) ? 1 : 0;      // kg boundary at 768 (= 48*16)
            int rem = i - akg*768;
            int r = rem >> 4, q = rem & 15;
            int kO = kofs + (2*t + akg) * 64;
            int gk = kO + q*4;
            float4 v = make_float4(0.f, 0.f, 0.f, 0.f);
            int m = m0 + r;
            if (m < M) {
                int b = m / P, left = m - b*P;
                int ci = cellIdx(b, left, L);
                v = (!bil || gk < 512)
                    ? *(const float4*)(g_chartH + (size_t)ci*HD + (gk & 511))
                    : *(const float4*)(g_chartC + (size_t)ci*HD + (gk - 512));
            }
            __nv_bfloat16 h0 = __float2bfloat16(v.x);
            __nv_bfloat16 h1 = __float2bfloat16(v.y);
            __nv_bfloat16 h2 = __float2bfloat16(v.z);
            __nv_bfloat16 h3 = __float2bfloat16(v.w);
            uint32_t hi0 = (uint32_t)__bfloat16_as_ushort(h0) | ((uint32_t)__bfloat16_as_ushort(h1) << 16);
            uint32_t hi1 = (uint32_t)__bfloat16_as_ushort(h2) | ((uint32_t)__bfloat16_as_ushort(h3) << 16);
            __nv_bfloat16 l0 = __float2bfloat16(v.x - __bfloat162float(h0));
            __nv_bfloat16 l1 = __float2bfloat16(v.y - __bfloat162float(h1));
            __nv_bfloat16 l2 = __float2bfloat16(v.z - __bfloat162float(h2));
            __nv_bfloat16 l3 = __float2bfloat16(v.w - __bfloat162float(h3));
            uint32_t lo0 = (uint32_t)__bfloat16_as_ushort(l0) | ((uint32_t)__bfloat16_as_ushort(l1) << 16);
            uint32_t lo1 = (uint32_t)__bfloat16_as_ushort(l2) | ((uint32_t)__bfloat16_as_ushort(l3) << 16);
            __nv_bfloat16* pH = sA + ((akg*2 + 0)*48 + r)*72 + q*4;
            __nv_bfloat16* pL = sA + ((akg*2 + 1)*48 + r)*72 + q*4;
            *(uint2*)pH = make_uint2(hi0, hi1);
            *(uint2*)pL = make_uint2(lo0, lo1);
        }
        // ---- stage B (bf16 planes), both kg chunks: 1024 uint4 ----
        for (int i = tid; i < 2*2*32*8; i += 256) {
            int bkg = i >> 9;                  // 512 per kg
            int rem = i - bkg*512;
            int pl = rem >> 8;
            int rr = (rem >> 3) & 31, j = rem & 7;
            int kO = kofs + (2*t + bkg) * 64;
            const __nv_bfloat16* src = (pl ? Wl : Wh) + (size_t)(nrow0 + rr)*wK + kO + j*8;
            __nv_bfloat16* dst = sB + ((bkg*2 + pl)*32 + rr)*72 + j*8;
            *(uint4*)dst = *(const uint4*)src;
        }
        __syncthreads();

        // ---- compute my kg's chunk ----
        const __nv_bfloat16* aH = sA + (kg*2 + 0)*48*72;
        const __nv_bfloat16* aL = sA + (kg*2 + 1)*48*72;
        const __nv_bfloat16* bH = sB + (kg*2 + 0)*32*72;
        const __nv_bfloat16* bL = sB + (kg*2 + 1)*32*72;
        #pragma unroll
        for (int s = 0; s < 4; s++) {
            const int kb = s*16 + ((lane & 3) << 1);
            const int ra = lane >> 2;
            const int nr = nw*8 + ra;
            uint32_t bh0 = lds32(bH + nr*72 + kb);
            uint32_t bh1 = lds32(bH + nr*72 + kb + 8);
            uint32_t bl0 = lds32(bL + nr*72 + kb);
            uint32_t bl1 = lds32(bL + nr*72 + kb + 8);
            #pragma unroll
            for (int mt = 0; mt < 3; mt++) {
                int r0 = mt*16 + ra;
                uint32_t a0 = lds32(aH + (r0    )*72 + kb);
                uint32_t a1 = lds32(aH + (r0 + 8)*72 + kb);
                uint32_t a2 = lds32(aH + (r0    )*72 + kb + 8);
                uint32_t a3 = lds32(aH + (r0 + 8)*72 + kb + 8);
                uint32_t c0 = lds32(aL + (r0    )*72 + kb);
                uint32_t c1 = lds32(aL + (r0 + 8)*72 + kb);
                uint32_t c2 = lds32(aL + (r0    )*72 + kb + 8);
                uint32_t c3 = lds32(aL + (r0 + 8)*72 + kb + 8);
                MMA_BF16(C[mt], a0, a1, a2, a3, bh0, bh1);
                MMA_BF16(C[mt], a0, a1, a2, a3, bl0, bl1);
                MMA_BF16(C[mt], c0, c1, c2, c3, bh0, bh1);
            }
        }
    }

    // ---- kg reduction: kg1 stores (into sA-aliased sC), kg0 adds + writes ----
    __syncthreads();
    if (kg == 1) {
        #pragma unroll
        for (int mt = 0; mt < 3; mt++) {
            float* p = sC + ((nw*3 + mt)*32 + lane)*4;
            p[0] = C[mt][0]; p[1] = C[mt][1]; p[2] = C[mt][2]; p[3] = C[mt][3];
        }
    }
    __syncthreads();
    if (kg == 0) {
        #pragma unroll
        for (int mt = 0; mt < 3; mt++) {
            const float* p = sC + ((nw*3 + mt)*32 + lane)*4;
            C[mt][0] += p[0]; C[mt][1] += p[1]; C[mt][2] += p[2]; C[mt][3] += p[3];
        }
        #pragma unroll
        for (int mt = 0; mt < 3; mt++) {
            #pragma unroll
            for (int h = 0; h < 2; h++) {
                int m = m0 + mt*16 + (lane >> 2) + h*8;
                if (m < M) {
                    int b = m / P, left = m - b*P;
                    int ci = cellIdx(b, left, L);
                    int o = oSeg + nw*8 + ((lane & 3) << 1);
                    *(float2*)(dstBase + (size_t)ci*stride + o) =
                        make_float2(C[mt][h*2], C[mt][h*2 + 1]);
                }
            }
        }
    }
}

// ---------------------------------------------------------------------------
// Pairs kernel: compat + softmax + gated combine. aL = aL1 + aL2 at use.
// ---------------------------------------------------------------------------
__global__ void pairsK(int L, int SPLIT, float* __restrict__ out) {
    const int P = NW - L;
    const int npair = BD*P;
    const int pairId = blockIdx.x % npair;
    const int s = blockIdx.x / npair;
    const int b = pairId / P, left = pairId - b*P;
    const int chunk = blockDim.x;
    const int e0 = s * chunk;

    __shared__ float s_w[24];
    __shared__ float s_comp[24];
    __shared__ int   s_offL[24], s_offR[24];

    const int tid = threadIdx.x, warp = tid >> 5, lane = tid & 31;
    const int nw = blockDim.x >> 5;

    for (int k = warp; k < L; k += nw) {
        int r = left + k + 1, rl = L - 1 - k;
        int cl = cellIdx(b, left, k), cr = cellIdx(b, r, rl);
        const float* a1 = g_aL1 + (size_t)cl*H2;
        const float* a2 = g_aL2 + (size_t)cl*H2;
        const float* rh = g_chartH + (size_t)cr*HD;
        const float* rc = g_chartC + (size_t)cr*HD;
        float acc = 0.0f;
        for (int i = lane; i < HD; i += 32) {
            acc = fmaf(a1[i] + a2[i], rh[i], acc);
            acc = fmaf(a1[HD + i] + a2[HD + i], rc[i], acc);
        }
        #pragma unroll
        for (int off = 16; off; off >>= 1)
            acc += __shfl_down_sync(0xffffffffu, acc, off);
        if (lane == 0) {
            s_comp[k] = acc + g_chartS[cl] + g_chartS[cr];
            s_offL[k] = cl; s_offR[k] = cr;
        }
    }
    __syncthreads();

    if (warp == 0) {
        float c = (lane < L) ? s_comp[lane] : -3.402823466e38f;
        float m = c;
        #pragma unroll
        for (int off = 16; off; off >>= 1)
            m = fmaxf(m, __shfl_xor_sync(0xffffffffu, m, off));
        float e = (lane < L) ? __expf(c - m) : 0.0f;
        float ssum = e;
        #pragma unroll
        for (int off = 16; off; off >>= 1)
            ssum += __shfl_xor_sync(0xffffffffu, ssum, off);
        float w = __fdividef(e, ssum);
        if (lane < L) s_w[lane] = w;
        float sn = (lane < L) ? w * c : 0.0f;
        #pragma unroll
        for (int off = 16; off; off >>= 1)
            sn += __shfl_xor_sync(0xffffffffu, sn, off);
        if (lane == 0 && s == 0) g_chartS[cellIdx(b, left, L)] = sn;
    }
    __syncthreads();

    {
        int e = e0 + tid;
        float b0 = g_bias[e],        b1 = g_bias[HD + e],  b2 = g_bias[2*HD + e];
        float b3 = g_bias[3*HD + e], b4 = g_bias[4*HD + e];
        float ah = 0.0f, ac = 0.0f;
        for (int k = 0; k < L; k++) {
            int cl = s_offL[k], cr = s_offR[k];
            const float* ui = g_Ui + (size_t)cl*H5;
            const float* us = g_Us + (size_t)cr*H5;
            float p0 = ui[e]        + us[e]        + b0;
            float p1 = ui[HD + e]   + us[HD + e]   + b1;
            float p2 = ui[2*HD + e] + us[2*HD + e] + b2;
            float p3 = ui[3*HD + e] + us[3*HD + e] + b3;
            float p4 = ui[4*HD + e] + us[4*HD + e] + b4;
            float lc = g_chartC[(size_t)cl*HD + e];
            float rc = g_chartC[(size_t)cr*HD + e];
            float ig = sigf(p0), lf = sigf(p1), rf = sigf(p2), og = sigf(p4);
            float gg = tanhx(p3);
            float mem = fmaf(lf, lc, fmaf(rf, rc, ig * gg));
            float hh = og * tanhx(mem);
            float w = s_w[k];
            ah = fmaf(w, hh, ah);
            ac = fmaf(w, mem, ac);
        }
        int cn = cellIdx(b, left, L);
        g_chartH[(size_t)cn*HD + e] = ah;
        g_chartC[(size_t)cn*HD + e] = ac;
        if (out) {
            out[b*H2 + e]      = ah;
            out[b*H2 + HD + e] = ac;
        }
    }
}

// ---------------------------------------------------------------------------
// Host side
// ---------------------------------------------------------------------------
static void launchProj(int L, int P) {
    int M = BD * P;
    int mB = (M + 47) / 48;
    mmaProj<<<dim3(224, mB), 256, SM_TOT>>>(L, P);
}

static int pickSplit(int P) {
    int np = BD * P;
    if (np >= 64) return 4;   // chunk 128
    return 8;                 // chunk 64
}

extern "C" void kernel_launch(void* const* d_in, const int* in_sizes, int n_in,
                              void* d_out, int out_size) {
    const float* seqt = (const float*)d_in[0];
    const float* Wi   = (const float*)d_in[1];
    const float* bi   = (const float*)d_in[2];
    const float* Ws   = (const float*)d_in[3];
    const float* bs   = (const float*)d_in[4];
    const float* Wbil = (const float*)d_in[5];
    float* out = (float*)d_out;

    // Setup: #0 convW, #1 initLeaves, #2 initBias => ncu (#3) = mmaProj(L=0)
    convW<<<dim3((5120*512 + 255)/256, 1, 2), 256>>>(Wi, Ws, Wbil);
    initLeaves<<<192, 256>>>(seqt);
    initBias<<<(H5 + 255)/256, 256>>>(bi, bs);

    launchProj(0, NW);

    for (int L = 1; L < NW; L++) {
        int P = NW - L;
        int SPLIT = pickSplit(P);
        pairsK<<<BD*P*SPLIT, HD/SPLIT>>>(L, SPLIT, (L == NW - 1) ? out : nullptr);
        if (L < NW - 1) launchProj(L, P);
    }
}